// round 14
// baseline (speedup 1.0000x reference)
#include <cuda_runtime.h>
#include <cooperative_groups.h>

namespace cg = cooperative_groups;

// FPS, torch_geometric semantics. 16 clouds x 16384 -> 4096 samples/cloud.
// 4-CTA cluster per cloud (64 CTAs), 4096 pts/CTA, min-dists in registers.
// WARP-DIRECT exchange: each warp's owner publishes {key, coords} into a
// 64-slot table replicated in all 4 CTAs (slot = global warp id), ONE
// cluster.sync per iteration, then all threads scan the 64 keys via redux and
// fetch the winner's coords by computed slot index. No __syncthreads at all.
// Slots parity-double-buffered; single-sync safety by forward dependency
// (publish(i+2) requires sync(i+1) which requires all reads of iter i done).
// Bit-exact arithmetic (validated R6+): d=(dx*dx+dy*dy)+dz*dz, RN, no FMA
// contraction, sub = add of negated. Keys: high=dist bits, low=~idx (first-
// occurrence argmax). redux two-step validated R12/R13.
// Output: float32 values of global indices.

#define N_CLOUDS 16
#define PTS      16384
#define M_SAMP   4096
#define THREADS  512
#define CL       4
#define QTR      4096
#define PAIRS    4
#define NW       16          // warps per CTA
#define NSLOT    64          // warps per cluster

__device__ __forceinline__ unsigned long long pack2(float lo, float hi) {
    unsigned long long r;
    asm("mov.b64 %0, {%1, %2};" : "=l"(r) : "f"(lo), "f"(hi));
    return r;
}
__device__ __forceinline__ void unpack2(unsigned long long v, float& lo, float& hi) {
    asm("mov.b64 {%0, %1}, %2;" : "=f"(lo), "=f"(hi) : "l"(v));
}
__device__ __forceinline__ unsigned long long add2(unsigned long long a, unsigned long long b) {
    unsigned long long r;
    asm("add.rn.f32x2 %0, %1, %2;" : "=l"(r) : "l"(a), "l"(b));
    return r;
}
__device__ __forceinline__ unsigned long long mul2(unsigned long long a, unsigned long long b) {
    unsigned long long r;
    asm("mul.rn.f32x2 %0, %1, %2;" : "=l"(r) : "l"(a), "l"(b));
    return r;
}
__device__ __forceinline__ unsigned int smem_u32(const void* p) {
    unsigned int a;
    asm("{ .reg .u64 t; cvta.to.shared.u64 t, %1; cvt.u32.u64 %0, t; }" : "=r"(a) : "l"(p));
    return a;
}
__device__ __forceinline__ unsigned int mapa_u32(unsigned int local_addr, unsigned int peer) {
    unsigned int r;
    asm("mapa.shared::cluster.u32 %0, %1, %2;" : "=r"(r) : "r"(local_addr), "r"(peer));
    return r;
}
__device__ __forceinline__ unsigned int redux_umax(unsigned int v) {
    unsigned int r;
    asm("redux.sync.max.u32 %0, %1, 0xffffffff;" : "=r"(r) : "r"(v));
    return r;
}

// 24-byte warp record: [0]=key u64 (bits<<32|inv), [8]=xy u64, [16]=z f32 (+pad)
#define SLOT_B 24

__global__ __launch_bounds__(THREADS, 1) __cluster_dims__(CL, 1, 1)
void fps_kernel(const float* __restrict__ pos, float* __restrict__ out)
{
    __shared__ __align__(8) unsigned char slots[2][NSLOT * SLOT_B];

    cg::cluster_group cluster = cg::this_cluster();
    const unsigned rank = cluster.block_rank();          // 0..3
    const int b    = blockIdx.x >> 2;                    // cloud id
    const int base = (int)rank * QTR;

    const int t    = threadIdx.x;
    const int lane = t & 31;
    const int wid  = t >> 5;
    const float* p = pos + (size_t)b * PTS * 3;

    const unsigned int slots_a = smem_u32(&slots[0][0]);
    // This warp's slot byte offset within a parity bank.
    const unsigned int myslot_off = (unsigned)((int)rank * NW + wid) * SLOT_B;

    // This thread's 8 points: cloud-local index g = base + t + (k<<9), k=0..7.
    unsigned long long CX[PAIRS], CY[PAIRS], CZ[PAIRS];
    float d[2 * PAIRS];
    const float INF = __int_as_float(0x7f800000);

#pragma unroll
    for (int pr = 0; pr < PAIRS; ++pr) {
        int g0 = base + t + ((2 * pr)     << 9);
        int g1 = base + t + ((2 * pr + 1) << 9);
        CX[pr] = pack2(p[3 * g0 + 0], p[3 * g1 + 0]);
        CY[pr] = pack2(p[3 * g0 + 1], p[3 * g1 + 1]);
        CZ[pr] = pack2(p[3 * g0 + 2], p[3 * g1 + 2]);
        d[2 * pr]     = INF;
        d[2 * pr + 1] = INF;
    }

    // First pick: cloud-local index 0 (broadcast global load).
    float sx = p[0], sy = p[1], sz = p[2];
    if (t == 0 && rank == 0) out[b * M_SAMP] = (float)(b * PTS);

    cluster.sync();   // cluster alive before first DSMEM publish

    for (int i = 1; i < M_SAMP; ++i) {
        const unsigned long long nx2 = pack2(-sx, -sx);
        const unsigned long long ny2 = pack2(-sy, -sy);
        const unsigned long long nz2 = pack2(-sz, -sz);

        float best = 0.0f;
        int jj = 0;

#pragma unroll
        for (int pr = 0; pr < PAIRS; ++pr) {
            unsigned long long dx = add2(CX[pr], nx2);       // exact sub
            unsigned long long dy = add2(CY[pr], ny2);
            unsigned long long dz = add2(CZ[pr], nz2);
            unsigned long long s  = add2(add2(mul2(dx, dx), mul2(dy, dy)), mul2(dz, dz));
            float lo, hi;
            unpack2(s, lo, hi);
            {
                float nd = fminf(d[2 * pr], lo);
                d[2 * pr] = nd;
                bool c = nd > best; best = c ? nd : best; jj = c ? 2 * pr : jj;
            }
            {
                float nd = fminf(d[2 * pr + 1], hi);
                d[2 * pr + 1] = nd;
                bool c = nd > best; best = c ? nd : best; jj = c ? 2 * pr + 1 : jj;
            }
        }

        const unsigned int gidx   = (unsigned int)(base + t) + ((unsigned int)jj << 9);
        const unsigned int mybits = __float_as_uint(best);
        const unsigned int myinv  = 0xFFFFFFFFu - gidx;

        // Warp argmax (bit-identical to u64 key max; validated R12/R13).
        const unsigned int wbits = redux_umax(mybits);
        const unsigned int winv  = redux_umax(mybits == wbits ? myinv : 0u);

        const int par = i & 1;
        const unsigned int bank = (unsigned)par * (NSLOT * SLOT_B);

        // Unique warp owner publishes {key, coords} to its slot in ALL 4 CTAs.
        if (mybits == wbits && myinv == winv) {
            const int prw = jj >> 1;
            const int hw  = jj & 1;
            float wx = 0.f, wy = 0.f, wz = 0.f;
#pragma unroll
            for (int pr = 0; pr < PAIRS; ++pr) {
                if (pr == prw) {
                    float l0, h0, l1, h1, l2, h2;
                    unpack2(CX[pr], l0, h0);
                    unpack2(CY[pr], l1, h1);
                    unpack2(CZ[pr], l2, h2);
                    wx = hw ? h0 : l0;
                    wy = hw ? h1 : l1;
                    wz = hw ? h2 : l2;
                }
            }
            const unsigned long long key64 =
                ((unsigned long long)wbits << 32) | (unsigned long long)winv;
            const unsigned long long xy = pack2(wx, wy);
            const unsigned int myaddr = slots_a + bank + myslot_off;
#pragma unroll
            for (unsigned r = 0; r < CL; ++r) {
                const unsigned int rs = mapa_u32(myaddr, r);
                asm volatile("st.shared::cluster.b64 [%0],    %1;" :: "r"(rs), "l"(key64) : "memory");
                asm volatile("st.shared::cluster.b64 [%0+8],  %1;" :: "r"(rs), "l"(xy)    : "memory");
                asm volatile("st.shared::cluster.f32 [%0+16], %1;" :: "r"(rs), "f"(wz)    : "memory");
            }
        }

        // THE one barrier: orders all publishes before all reads, cluster-wide.
        cluster.sync();

        // Scan 64 keys: each lane pre-maxes 2 slots, then two redux.
        const unsigned int sb = slots_a + bank;
        unsigned long long k0, k1;
        asm volatile("ld.shared.b64 %0, [%1];" : "=l"(k0)
                     : "r"(sb + (unsigned)(2 * lane)     * SLOT_B) : "memory");
        asm volatile("ld.shared.b64 %0, [%1];" : "=l"(k1)
                     : "r"(sb + (unsigned)(2 * lane + 1) * SLOT_B) : "memory");
        const unsigned long long km = (k1 > k0) ? k1 : k0;
        const unsigned int hb = (unsigned int)(km >> 32);
        const unsigned int rb = redux_umax(hb);
        const unsigned int ri = redux_umax(hb == rb ? (unsigned int)km : 0u);

        const unsigned int gw = 0xFFFFFFFFu - ri;            // cloud-local winner idx
        // Winner's slot: rank = gw>>12, warp = (gw&511)>>5.
        const unsigned int wslot = ((gw >> 12) << 4) | ((gw & 511u) >> 5);
        const unsigned int wa = sb + wslot * SLOT_B;
        unsigned long long wxy;
        float wz;
        asm volatile("ld.shared.b64 %0, [%1+8];"  : "=l"(wxy) : "r"(wa) : "memory");
        asm volatile("ld.shared.f32 %0, [%1+16];" : "=f"(wz)  : "r"(wa) : "memory");
        unpack2(wxy, sx, sy);
        sz = wz;

        if (t == 0 && rank == 0)
            out[b * M_SAMP + i] = (float)(b * PTS + (int)gw);
    }
}

extern "C" void kernel_launch(void* const* d_in, const int* in_sizes, int n_in,
                              void* d_out, int out_size)
{
    // Resolve pos BY SIZE (786432 floats), robust to input ordering.
    const float* pos = nullptr;
    for (int i = 0; i < n_in; ++i) {
        if (in_sizes[i] == N_CLOUDS * PTS * 3) { pos = (const float*)d_in[i]; break; }
    }
    if (!pos) pos = (const float*)d_in[0];

    float* out = (float*)d_out;   // [N_CLOUDS*M_SAMP] float32 index values

    fps_kernel<<<N_CLOUDS * CL, THREADS>>>(pos, out);
}

// round 15
// speedup vs baseline: 2.0381x; 2.0381x over previous
#include <cuda_runtime.h>
#include <cooperative_groups.h>

namespace cg = cooperative_groups;

// FPS, torch_geometric semantics. 16 clouds x 16384 -> 4096 samples/cloud.
// 4-CTA cluster per cloud (64 CTAs), 4096 pts/CTA, min-dists in registers.
// Protocol (R13-proven): warp redux -> skeys -> __syncthreads -> CTA scan ->
// unique owner publishes ONE record to all 4 CTAs -> cluster.sync -> combine.
// This round: both serial scans (16 warp keys, 4 slot keys) replaced by
// redux.sync.max.u32 pairs (bit-identical key semantics, validated R12/R13).
// Bit-exact arithmetic (validated R6+): d=(dx*dx+dy*dy)+dz*dz, RN, no FMA
// contraction, sub = add of negated. Keys: high=dist bits, low=~idx (first-
// occurrence argmax). Output: float32 values of global indices.

#define N_CLOUDS 16
#define PTS      16384
#define M_SAMP   4096
#define THREADS  512
#define CL       4
#define QTR      4096
#define PAIRS    4       // 8 points per thread = 4 f32x2 pairs
#define NW       16      // warps per CTA

__device__ __forceinline__ unsigned long long pack2(float lo, float hi) {
    unsigned long long r;
    asm("mov.b64 %0, {%1, %2};" : "=l"(r) : "f"(lo), "f"(hi));
    return r;
}
__device__ __forceinline__ void unpack2(unsigned long long v, float& lo, float& hi) {
    asm("mov.b64 {%0, %1}, %2;" : "=f"(lo), "=f"(hi) : "l"(v));
}
// Packed IEEE RN f32x2 ops (sm_100+): bit-identical to scalar FADD/FMUL.
__device__ __forceinline__ unsigned long long add2(unsigned long long a, unsigned long long b) {
    unsigned long long r;
    asm("add.rn.f32x2 %0, %1, %2;" : "=l"(r) : "l"(a), "l"(b));
    return r;
}
__device__ __forceinline__ unsigned long long mul2(unsigned long long a, unsigned long long b) {
    unsigned long long r;
    asm("mul.rn.f32x2 %0, %1, %2;" : "=l"(r) : "l"(a), "l"(b));
    return r;
}
__device__ __forceinline__ unsigned int redux_umax(unsigned int v) {
    unsigned int r;
    asm("redux.sync.max.u32 %0, %1, 0xffffffff;" : "=r"(r) : "r"(v));
    return r;
}

struct __align__(8) Slot { unsigned long long key; unsigned long long xy; float z_; };

__global__ __launch_bounds__(THREADS, 1) __cluster_dims__(CL, 1, 1)
void fps_kernel(const float* __restrict__ pos, float* __restrict__ out)
{
    __shared__ unsigned long long skeys[2][NW];   // [parity][warp] reduced keys
    __shared__ Slot slots[2][CL];                 // [parity][rank] exchange records

    cg::cluster_group cluster = cg::this_cluster();
    const unsigned rank = cluster.block_rank();          // 0..3
    const int b    = blockIdx.x >> 2;                    // cloud id
    const int base = (int)rank * QTR;

    const int t    = threadIdx.x;
    const int lane = t & 31;
    const int wid  = t >> 5;
    const float* p = pos + (size_t)b * PTS * 3;

    // This thread's 8 points: cloud-local index g = base + t + (k<<9), k=0..7.
    unsigned long long CX[PAIRS], CY[PAIRS], CZ[PAIRS];
    float d[2 * PAIRS];
    const float INF = __int_as_float(0x7f800000);

#pragma unroll
    for (int pr = 0; pr < PAIRS; ++pr) {
        int g0 = base + t + ((2 * pr)     << 9);
        int g1 = base + t + ((2 * pr + 1) << 9);
        CX[pr] = pack2(p[3 * g0 + 0], p[3 * g1 + 0]);
        CY[pr] = pack2(p[3 * g0 + 1], p[3 * g1 + 1]);
        CZ[pr] = pack2(p[3 * g0 + 2], p[3 * g1 + 2]);
        d[2 * pr]     = INF;
        d[2 * pr + 1] = INF;
    }

    // First pick: cloud-local index 0 (L1-broadcast global load).
    float sx = p[0], sy = p[1], sz = p[2];
    if (t == 0 && rank == 0) out[b * M_SAMP] = (float)(b * PTS);

    cluster.sync();   // cluster alive before first DSMEM publish

    for (int i = 1; i < M_SAMP; ++i) {
        const unsigned long long nx2 = pack2(-sx, -sx);
        const unsigned long long ny2 = pack2(-sy, -sy);
        const unsigned long long nz2 = pack2(-sz, -sz);

        float best = 0.0f;
        int jj = 0;

#pragma unroll
        for (int pr = 0; pr < PAIRS; ++pr) {
            unsigned long long dx = add2(CX[pr], nx2);       // exact sub
            unsigned long long dy = add2(CY[pr], ny2);
            unsigned long long dz = add2(CZ[pr], nz2);
            unsigned long long s  = add2(add2(mul2(dx, dx), mul2(dy, dy)), mul2(dz, dz));
            float lo, hi;
            unpack2(s, lo, hi);
            {
                float nd = fminf(d[2 * pr], lo);
                d[2 * pr] = nd;
                bool c = nd > best; best = c ? nd : best; jj = c ? 2 * pr : jj;
            }
            {
                float nd = fminf(d[2 * pr + 1], hi);
                d[2 * pr + 1] = nd;
                bool c = nd > best; best = c ? nd : best; jj = c ? 2 * pr + 1 : jj;
            }
        }

        // Key: high = dist bits (>=0, order-preserving), low = ~cloud_local_idx
        // (ties break toward the LOWEST index == jnp.argmax first-occurrence).
        const unsigned int gidx   = (unsigned int)(base + t) + ((unsigned int)jj << 9);
        const unsigned int mybits = __float_as_uint(best);
        const unsigned int myinv  = 0xFFFFFFFFu - gidx;

        // Warp argmax via 2 hardware reductions (bit-identical to u64 max).
        const unsigned int wbits = redux_umax(mybits);
        const unsigned int winv  = redux_umax(mybits == wbits ? myinv : 0u);

        const int par = i & 1;
        if (lane == 0)
            skeys[par][wid] = ((unsigned long long)wbits << 32) | winv;
        __syncthreads();                                   // (A)

        // CTA scan of 16 warp keys via redux (replaces serial u64 scan).
        unsigned long long kw = (lane < NW) ? skeys[par][lane] : 0ull;
        const unsigned int chb = (unsigned int)(kw >> 32);
        const unsigned int crb = redux_umax(chb);
        const unsigned int cri = redux_umax(chb == crb ? (unsigned int)kw : 0u);

        // UNIQUE owner (its pre-reduction key == CTA max) publishes one record
        // {key, xy, z} to its slot in ALL CTAs (local + 3 peers via DSMEM).
        if (mybits == crb && myinv == cri) {
            const int prw = jj >> 1;
            const int hw  = jj & 1;
            float wx = 0.f, wy = 0.f, wz = 0.f;
#pragma unroll
            for (int pr = 0; pr < PAIRS; ++pr) {
                if (pr == prw) {
                    float l0, h0, l1, h1, l2, h2;
                    unpack2(CX[pr], l0, h0);
                    unpack2(CY[pr], l1, h1);
                    unpack2(CZ[pr], l2, h2);
                    wx = hw ? h0 : l0;
                    wy = hw ? h1 : l1;
                    wz = hw ? h2 : l2;
                }
            }
            const unsigned long long key64 =
                ((unsigned long long)crb << 32) | (unsigned long long)cri;
            const unsigned long long xy = pack2(wx, wy);
            // Local record
            slots[par][rank].key = key64;
            slots[par][rank].xy  = xy;
            slots[par][rank].z_  = wz;
            // Peer records via DSMEM (ordering provided by cluster.sync below)
#pragma unroll
            for (unsigned pr_ = 1; pr_ < CL; ++pr_) {
                const unsigned peer = (rank + pr_) & (CL - 1);
                Slot* rs = cluster.map_shared_rank(&slots[par][rank], peer);
                rs->key = key64;
                rs->xy  = xy;
                rs->z_  = wz;
            }
        }

        // Orders publishes before reads; second barrier of the iteration
        // (skeys and slots are parity-double-buffered).
        cluster.sync();

        // Cluster combine of 4 slot keys via redux.
        const unsigned long long ks = (lane < CL) ? slots[par][lane].key : 0ull;
        const unsigned int ghb = (unsigned int)(ks >> 32);
        const unsigned int grb = redux_umax(ghb);
        const unsigned int gri = redux_umax(ghb == grb ? (unsigned int)ks : 0u);

        const unsigned int gw = 0xFFFFFFFFu - gri;   // cloud-local winner idx
        const unsigned int wslot = gw >> 12;         // winner's CTA rank = slot
        unpack2(slots[par][wslot].xy, sx, sy);
        sz = slots[par][wslot].z_;

        if (t == 0 && rank == 0)
            out[b * M_SAMP + i] = (float)(b * PTS + (int)gw);
    }
}

extern "C" void kernel_launch(void* const* d_in, const int* in_sizes, int n_in,
                              void* d_out, int out_size)
{
    // Resolve pos BY SIZE (786432 floats), robust to input ordering.
    const float* pos = nullptr;
    for (int i = 0; i < n_in; ++i) {
        if (in_sizes[i] == N_CLOUDS * PTS * 3) { pos = (const float*)d_in[i]; break; }
    }
    if (!pos) pos = (const float*)d_in[0];

    float* out = (float*)d_out;   // [N_CLOUDS*M_SAMP] float32 index values

    fps_kernel<<<N_CLOUDS * CL, THREADS>>>(pos, out);
}